// round 1
// baseline (speedup 1.0000x reference)
#include <cuda_runtime.h>

#define HIDDEN 32
#define FF 40
#define TSTEPS 512
#define BATCH 16384
#define BLOCK 128
#define NJP (FF/2)      /* 20 packed pairs over FF dim  */
#define NHP (HIDDEN/2)  /* 16 packed pairs over hidden  */

typedef unsigned long long u64;

__device__ __forceinline__ u64 pk(float a, float b) {
    u64 r; asm("mov.b64 %0,{%1,%2};" : "=l"(r) : "f"(a), "f"(b)); return r;
}
__device__ __forceinline__ void upk(u64 v, float& a, float& b) {
    asm("mov.b64 {%0,%1},%2;" : "=f"(a), "=f"(b) : "l"(v));
}
__device__ __forceinline__ u64 f2fma(u64 a, u64 b, u64 c) {
    u64 d; asm("fma.rn.f32x2 %0,%1,%2,%3;" : "=l"(d) : "l"(a), "l"(b), "l"(c)); return d;
}
// sigmoid(x) = 1/(1+2^(-x*log2e)); ex2/rcp approx are ~1e-6 rel err — far inside 1e-3 budget
__device__ __forceinline__ float sigm(float x) {
    float e, r;
    asm("ex2.approx.ftz.f32 %0,%1;" : "=f"(e) : "f"(x * -1.4426950408889634f));
    asm("rcp.approx.ftz.f32 %0,%1;" : "=f"(r) : "f"(1.0f + e));
    return r;
}

__global__ void __launch_bounds__(BLOCK, 1) rnn_f32x2_kernel(
    const float* __restrict__ inp,
    const float* __restrict__ W1hh, const float* __restrict__ b1hh,
    const float* __restrict__ W2hh, const float* __restrict__ b2hh,
    const float* __restrict__ W1ho, const float* __restrict__ b1ho,
    const float* __restrict__ W2ho, const float* __restrict__ b2ho,
    float* __restrict__ out)
{
    // Weights as f32x2 pairs (adjacent output columns are adjacent in row-major
    // storage, so a plain u64 copy gives ready-made packed operands).
    __shared__ u64 sW1hh[33 * NJP];   // [33][20] pairs
    __shared__ u64 sW1ho[33 * NJP];
    __shared__ u64 sW2hh[FF * NHP];   // [40][16] pairs
    __shared__ u64 sW2ho[NJP];
    __shared__ u64 sb1hh[NJP], sb1ho[NJP], sb2hh[NHP];
    // Per-thread scratch column: holds c=[h,u] (33) during layer1, then s (40)
    // during layer2. Lane-stride-1 layout -> conflict-free, fully thread-private.
    __shared__ float buf[FF * BLOCK];

    const int tid = threadIdx.x;

    for (int i = tid; i < 33 * NJP; i += BLOCK) {
        sW1hh[i] = ((const u64*)W1hh)[i];
        sW1ho[i] = ((const u64*)W1ho)[i];
    }
    for (int i = tid; i < FF * NHP; i += BLOCK) sW2hh[i] = ((const u64*)W2hh)[i];
    if (tid < NJP) {
        sW2ho[tid] = ((const u64*)W2ho)[tid];
        sb1hh[tid] = ((const u64*)b1hh)[tid];
        sb1ho[tid] = ((const u64*)b1ho)[tid];
    }
    if (tid < NHP) sb2hh[tid] = ((const u64*)b2hh)[tid];
    const float bias_o = b2ho[0];
    __syncthreads();

    const int e = blockIdx.x * BLOCK + tid;
    if (e >= BATCH) return;
    const float* __restrict__ ip = inp + (size_t)e * TSTEPS;
    float* __restrict__ op = out + (size_t)e * TSTEPS;

    // h0 = 0
    #pragma unroll
    for (int i = 0; i < HIDDEN; i++) buf[i * BLOCK + tid] = 0.0f;

    #pragma unroll 1
    for (int t = 0; t < TSTEPS; t++) {
        // c = [h (0..31), u (32)]
        buf[HIDDEN * BLOCK + tid] = ip[t];

        // ---- layer 1, both heads fused: z = c @ W1 + b1 (packed over j) ----
        u64 zhh[NJP], zho[NJP];
        #pragma unroll
        for (int jp = 0; jp < NJP; jp++) { zhh[jp] = sb1hh[jp]; zho[jp] = sb1ho[jp]; }

        #pragma unroll 1
        for (int i = 0; i < 33; i++) {
            float c = buf[i * BLOCK + tid];
            u64 cd = pk(c, c);
            const u64* wa = sW1hh + i * NJP;
            const u64* wb = sW1ho + i * NJP;
            #pragma unroll
            for (int jp = 0; jp < NJP; jp++) {
                zhh[jp] = f2fma(cd, wa[jp], zhh[jp]);
                zho[jp] = f2fma(cd, wb[jp], zho[jp]);
            }
        }

        // ---- s_hh = sigmoid(zhh) -> buf (c is dead now) ----
        #pragma unroll
        for (int jp = 0; jp < NJP; jp++) {
            float a, b; upk(zhh[jp], a, b);
            buf[(2 * jp) * BLOCK + tid]     = sigm(a);
            buf[(2 * jp + 1) * BLOCK + tid] = sigm(b);
        }

        // ---- output head: out = sigmoid(zho) @ W2ho + b2ho (packed dot) ----
        u64 acc2 = pk(0.0f, 0.0f);
        #pragma unroll
        for (int jp = 0; jp < NJP; jp++) {
            float a, b; upk(zho[jp], a, b);
            u64 sp = pk(sigm(a), sigm(b));
            acc2 = f2fma(sp, sW2ho[jp], acc2);
        }
        {
            float a0, a1; upk(acc2, a0, a1);
            op[t] = a0 + a1 + bias_o;
        }

        // ---- layer 2: h_new = s_hh @ W2hh + b2hh (packed over output pairs) ----
        u64 hn[NHP];
        #pragma unroll
        for (int p = 0; p < NHP; p++) hn[p] = sb2hh[p];

        #pragma unroll 1
        for (int k = 0; k < FF; k++) {
            float s = buf[k * BLOCK + tid];
            u64 sd = pk(s, s);
            const u64* w = sW2hh + k * NHP;
            #pragma unroll
            for (int p = 0; p < NHP; p++) hn[p] = f2fma(sd, w[p], hn[p]);
        }

        // ---- write h back for next step (s is dead now) ----
        #pragma unroll
        for (int p = 0; p < NHP; p++) {
            float a, b; upk(hn[p], a, b);
            buf[(2 * p) * BLOCK + tid]     = a;
            buf[(2 * p + 1) * BLOCK + tid] = b;
        }
    }
}

extern "C" void kernel_launch(void* const* d_in, const int* in_sizes, int n_in,
                              void* d_out, int out_size) {
    const float* inp  = (const float*)d_in[0];
    const float* W1hh = (const float*)d_in[1];
    const float* b1hh = (const float*)d_in[2];
    const float* W2hh = (const float*)d_in[3];
    const float* b2hh = (const float*)d_in[4];
    const float* W1ho = (const float*)d_in[5];
    const float* b1ho = (const float*)d_in[6];
    const float* W2ho = (const float*)d_in[7];
    const float* b2ho = (const float*)d_in[8];
    float* out = (float*)d_out;

    dim3 grid(BATCH / BLOCK);   // 128 blocks x 128 threads = 16384 threads
    dim3 block(BLOCK);
    rnn_f32x2_kernel<<<grid, block>>>(inp, W1hh, b1hh, W2hh, b2hh,
                                      W1ho, b1ho, W2ho, b2ho, out);
}